// round 1
// baseline (speedup 1.0000x reference)
#include <cuda_runtime.h>
#include <math.h>

#define BB 2
#define SS 2048
#define DD 1024
#define HH 16
#define HDIM 64

// Scratch (module-static device allocations; runtime alloc is forbidden)
__device__ float g_q[BB * HH * SS * HDIM];
__device__ float g_k[BB * HH * SS * HDIM];
__device__ float g_v[BB * HH * SS * HDIM];
__device__ float g_ctx[BB * SS * DD];

// ---------------------------------------------------------------------------
// GEMM: out = A[4096,1024] @ W[1024,1024]^T (+bias). Both A and W are K-major
// (NT layout). Tiles 64x64, K-chunks of 16, 256 threads, 4x4 microtile.
// Shared operands stored transposed [k][m]/[k][n] with XOR swizzle at float4
// granularity: physical col = (((m>>2) ^ (k>>2)) & 15)*4 + (m&3).
// reshape=1: scatter out to [B,H,S,64] (n-tile == one head since 64 | n0).
// ---------------------------------------------------------------------------
__global__ void __launch_bounds__(256)
gemm64(const float* __restrict__ A, const float* __restrict__ Wt,
       const float* __restrict__ bias, float* __restrict__ out, int reshape)
{
    __shared__ float As[16][64];
    __shared__ float Bs[16][64];

    const int tid = threadIdx.x;
    const int tx = tid & 15;
    const int ty = tid >> 4;
    const int m0 = blockIdx.y << 6;
    const int n0 = blockIdx.x << 6;

    const int lr = tid >> 2;         // 0..63 row within tile
    const int lk = (tid & 3) << 2;   // 0,4,8,12 k-offset (float4)

    float acc[4][4] = {};

    const float* Aptr = A + (m0 + lr) * DD + lk;
    const float* Bptr = Wt + (n0 + lr) * DD + lk;

    for (int k0 = 0; k0 < DD; k0 += 16) {
        float4 av = *(const float4*)(Aptr + k0);
        float4 bv = *(const float4*)(Bptr + k0);
        float avv[4] = {av.x, av.y, av.z, av.w};
        float bvv[4] = {bv.x, bv.y, bv.z, bv.w};
#pragma unroll
        for (int i = 0; i < 4; i++) {
            int k = lk + i;
            int col = ((((lr >> 2) ^ (k >> 2)) & 15) << 2) | (lr & 3);
            As[k][col] = avv[i];
            Bs[k][col] = bvv[i];
        }
        __syncthreads();
#pragma unroll
        for (int kk = 0; kk < 16; kk++) {
            float4 a4 = *(const float4*)&As[kk][((ty ^ (kk >> 2)) & 15) << 2];
            float4 b4 = *(const float4*)&Bs[kk][((tx ^ (kk >> 2)) & 15) << 2];
            float a[4] = {a4.x, a4.y, a4.z, a4.w};
            float b[4] = {b4.x, b4.y, b4.z, b4.w};
#pragma unroll
            for (int i = 0; i < 4; i++)
#pragma unroll
                for (int j = 0; j < 4; j++)
                    acc[i][j] = fmaf(a[i], b[j], acc[i][j]);
        }
        __syncthreads();
    }

    float bj[4] = {0.f, 0.f, 0.f, 0.f};
    if (bias) {
#pragma unroll
        for (int j = 0; j < 4; j++) bj[j] = bias[n0 + (tx << 2) + j];
    }

    if (reshape) {
        const int h = n0 >> 6;
#pragma unroll
        for (int i = 0; i < 4; i++) {
            int m = m0 + (ty << 2) + i;
            int b = m >> 11;           // S = 2048
            int s = m & 2047;
            float4 o = make_float4(acc[i][0], acc[i][1], acc[i][2], acc[i][3]);
            *(float4*)(out + ((size_t)((b * HH + h) * SS + s)) * HDIM + (tx << 2)) = o;
        }
    } else {
#pragma unroll
        for (int i = 0; i < 4; i++) {
            int m = m0 + (ty << 2) + i;
            float4 o = make_float4(acc[i][0] + bj[0], acc[i][1] + bj[1],
                                   acc[i][2] + bj[2], acc[i][3] + bj[3]);
            *(float4*)(out + (size_t)m * DD + n0 + (tx << 2)) = o;
        }
    }
}

// ---------------------------------------------------------------------------
// Causal flash attention. One CTA per (q-tile of 64 rows, b*h). 256 threads,
// 16x16 grid, 4x4 microtiles. Online softmax state per row (replicated over
// the 16 tx lanes of each row; reductions via shfl.xor within 16-lane groups).
// Smem: Qs [d][row] swizzled, KP [d][key] swizzled (reused as P [key][row]
// swizzled), Vs [key][d] natural. 3 x 16KB = 48KB static.
// ---------------------------------------------------------------------------
__global__ void __launch_bounds__(256)
attn_kernel(float* __restrict__ ctx)
{
    __shared__ float Qs[64][64];
    __shared__ float KP[64][64];
    __shared__ float Vs[64][64];

    const int tid = threadIdx.x;
    const int tx = tid & 15;
    const int ty = tid >> 4;
    const int bh = blockIdx.y;                 // b*H + h
    const int q0 = blockIdx.x << 6;

    const float* Qb = g_q + (size_t)bh * SS * HDIM;
    const float* Kb = g_k + (size_t)bh * SS * HDIM;
    const float* Vb = g_v + (size_t)bh * SS * HDIM;

    const int fr = tid >> 4;                   // 0..15 base row for fills
    const int fc = (tid & 15) << 2;            // float4 column

    // Load Q tile, transposed + swizzled: Qs[d][col(row,d)]
#pragma unroll
    for (int p = 0; p < 4; p++) {
        int r = fr + (p << 4);
        float4 v = *(const float4*)(Qb + (size_t)(q0 + r) * HDIM + fc);
        float vv[4] = {v.x, v.y, v.z, v.w};
#pragma unroll
        for (int i = 0; i < 4; i++) {
            int d = fc + i;
            Qs[d][((((r >> 2) ^ (d >> 2)) & 15) << 2) | (r & 3)] = vv[i];
        }
    }

    float m_i[4], l_i[4], o[4][4];
#pragma unroll
    for (int i = 0; i < 4; i++) {
        m_i[i] = -1e30f;
        l_i[i] = 0.f;
#pragma unroll
        for (int j = 0; j < 4; j++) o[i][j] = 0.f;
    }

    const int ktiles = (q0 >> 6) + 1;
    for (int kt = 0; kt < ktiles; kt++) {
        const int k0 = kt << 6;
        __syncthreads();   // previous PV reads finished; Q fill visible

        // Fill K (transposed+swizzled into KP) and V (natural)
#pragma unroll
        for (int p = 0; p < 4; p++) {
            int r = fr + (p << 4);
            float4 kv = *(const float4*)(Kb + (size_t)(k0 + r) * HDIM + fc);
            float kvv[4] = {kv.x, kv.y, kv.z, kv.w};
#pragma unroll
            for (int i = 0; i < 4; i++) {
                int d = fc + i;
                KP[d][((((r >> 2) ^ (d >> 2)) & 15) << 2) | (r & 3)] = kvv[i];
            }
            float4 vv = *(const float4*)(Vb + (size_t)(k0 + r) * HDIM + fc);
            *(float4*)&Vs[r][fc] = vv;
        }
        __syncthreads();

        // S = Q K^T  (dot over d = 64)
        float s[4][4] = {};
#pragma unroll
        for (int kk = 0; kk < 64; kk++) {
            float4 a4 = *(const float4*)&Qs[kk][((ty ^ (kk >> 2)) & 15) << 2];
            float4 b4 = *(const float4*)&KP[kk][((tx ^ (kk >> 2)) & 15) << 2];
            float a[4] = {a4.x, a4.y, a4.z, a4.w};
            float b[4] = {b4.x, b4.y, b4.z, b4.w};
#pragma unroll
            for (int i = 0; i < 4; i++)
#pragma unroll
                for (int j = 0; j < 4; j++)
                    s[i][j] = fmaf(a[i], b[j], s[i][j]);
        }

        // scale + causal mask (only the diagonal tile has k0 == q0)
        const bool diag = (kt == ktiles - 1);
#pragma unroll
        for (int i = 0; i < 4; i++)
#pragma unroll
            for (int j = 0; j < 4; j++) {
                s[i][j] *= 0.125f;   // 1/sqrt(64)
                if (diag && ((tx << 2) + j) > ((ty << 2) + i)) s[i][j] = -1e30f;
            }

        // online softmax update (rows owned by 16 tx lanes; reduce over them)
#pragma unroll
        for (int i = 0; i < 4; i++) {
            float rm = fmaxf(fmaxf(s[i][0], s[i][1]), fmaxf(s[i][2], s[i][3]));
#pragma unroll
            for (int off = 8; off > 0; off >>= 1)
                rm = fmaxf(rm, __shfl_xor_sync(0xffffffffu, rm, off));
            float mn = fmaxf(m_i[i], rm);
            float alpha = __expf(m_i[i] - mn);
            m_i[i] = mn;
            float rs = 0.f;
#pragma unroll
            for (int j = 0; j < 4; j++) {
                s[i][j] = __expf(s[i][j] - mn);
                rs += s[i][j];
            }
#pragma unroll
            for (int off = 8; off > 0; off >>= 1)
                rs += __shfl_xor_sync(0xffffffffu, rs, off);
            l_i[i] = l_i[i] * alpha + rs;
#pragma unroll
            for (int j = 0; j < 4; j++) o[i][j] *= alpha;
        }

        __syncthreads();  // all lanes done reading K from KP

        // Store P transposed+swizzled into KP: logical P[key][row]
#pragma unroll
        for (int j = 0; j < 4; j++) {
            int key = (tx << 2) + j;
            float4 pv = make_float4(s[0][j], s[1][j], s[2][j], s[3][j]);
            *(float4*)&KP[key][((ty ^ tx) & 15) << 2] = pv;
        }
        __syncthreads();

        // O += P @ V
#pragma unroll
        for (int kk = 0; kk < 64; kk++) {
            float4 a4 = *(const float4*)&KP[kk][((ty ^ (kk >> 2)) & 15) << 2];
            float4 b4 = *(const float4*)&Vs[kk][tx << 2];
            float a[4] = {a4.x, a4.y, a4.z, a4.w};
            float b[4] = {b4.x, b4.y, b4.z, b4.w};
#pragma unroll
            for (int i = 0; i < 4; i++)
#pragma unroll
                for (int j = 0; j < 4; j++)
                    o[i][j] = fmaf(a[i], b[j], o[i][j]);
        }
    }

    // Epilogue: ctx[b, s, h*64 + d] = o / l
    const int b = bh >> 4;     // H = 16
    const int h = bh & 15;
#pragma unroll
    for (int i = 0; i < 4; i++) {
        int row = q0 + (ty << 2) + i;
        float inv = 1.0f / l_i[i];
        float4 ov = make_float4(o[i][0] * inv, o[i][1] * inv,
                                o[i][2] * inv, o[i][3] * inv);
        *(float4*)(ctx + ((size_t)(b * SS + row)) * DD + (h << 6) + (tx << 2)) = ov;
    }
}

// ---------------------------------------------------------------------------
extern "C" void kernel_launch(void* const* d_in, const int* in_sizes, int n_in,
                              void* d_out, int out_size)
{
    const float* x  = (const float*)d_in[0];
    const float* Wq = (const float*)d_in[1];
    const float* Wk = (const float*)d_in[2];
    const float* Wv = (const float*)d_in[3];
    const float* Wo = (const float*)d_in[4];
    const float* bo = (const float*)d_in[5];
    float* out = (float*)d_out;

    float *q_p, *k_p, *v_p, *c_p;
    cudaGetSymbolAddress((void**)&q_p, g_q);
    cudaGetSymbolAddress((void**)&k_p, g_k);
    cudaGetSymbolAddress((void**)&v_p, g_v);
    cudaGetSymbolAddress((void**)&c_p, g_ctx);

    dim3 blk(256);
    dim3 gg(16, 64);           // N/64 x M/64  (M=4096, N=1024)

    gemm64<<<gg, blk>>>(x, Wq, nullptr, q_p, 1);
    gemm64<<<gg, blk>>>(x, Wk, nullptr, k_p, 1);
    gemm64<<<gg, blk>>>(x, Wv, nullptr, v_p, 1);

    attn_kernel<<<dim3(32, 32), blk>>>(c_p);   // 32 q-tiles x (B*H = 32)

    gemm64<<<gg, blk>>>(c_p, Wo, bo, out, 0);
}

// round 5
// speedup vs baseline: 3.0823x; 3.0823x over previous
#include <cuda_runtime.h>
#include <cuda_bf16.h>
#include <cstdint>
#include <math.h>

#define BB 2
#define SS 2048
#define DD 1024
#define HH 16
#define HDIM 64

__device__ float g_q[BB * HH * SS * HDIM];
__device__ float g_k[BB * HH * SS * HDIM];
__device__ float g_v[BB * HH * SS * HDIM];
__device__ float g_ctx[BB * SS * DD];

// fp32 -> tf32 (round to nearest) kept in a b32 register / stored as float bits
__device__ __forceinline__ uint32_t f2tf(float f) {
    uint32_t u;
    asm("cvt.rna.tf32.f32 %0, %1;" : "=r"(u) : "f"(f));
    return u;
}
__device__ __forceinline__ uint32_t fau(float f) { return __float_as_uint(f); }

// mma.sync m16n8k8 tf32, fp32 accumulate (in-place)
__device__ __forceinline__ void mma8(float* c, const uint32_t* a, const uint32_t* b) {
    asm volatile(
        "mma.sync.aligned.m16n8k8.row.col.f32.tf32.tf32.f32 "
        "{%0,%1,%2,%3},{%4,%5,%6,%7},{%8,%9},{%0,%1,%2,%3};"
        : "+f"(c[0]), "+f"(c[1]), "+f"(c[2]), "+f"(c[3])
        : "r"(a[0]), "r"(a[1]), "r"(a[2]), "r"(a[3]), "r"(b[0]), "r"(b[1]));
}

__device__ __forceinline__ void st_tf4(float* dst, float4 v) {
    uint4 t = make_uint4(f2tf(v.x), f2tf(v.y), f2tf(v.z), f2tf(v.w));
    *(uint4*)dst = t;
}

// ---------------------------------------------------------------------------
// tf32 tensor-core GEMM: out[4096,1024] = A @ W^T (+bias).
// CTA tile 128x128, K-chunk 32, 256 threads (8 warps, 64x32 each),
// reg-staged double-buffered smem, pad-4 row stride (36) => conflict-free
// fragment loads. reshape=1 scatters to [B,H,S,64].
// ---------------------------------------------------------------------------
#define GEMM_SMEM (73728)   // 2 buffers x (A 128x36 + B 128x36) floats

__global__ void __launch_bounds__(256)
gemm_tc(const float* __restrict__ A, const float* __restrict__ W,
        const float* __restrict__ bias, float* __restrict__ out, int reshape)
{
    extern __shared__ float sm[];
    const int tid = threadIdx.x;
    const int wid = tid >> 5, lane = tid & 31;
    const int g = lane >> 2, c = lane & 3;
    const int m0 = blockIdx.y << 7, n0 = blockIdx.x << 7;
    const int wm = (wid >> 2) << 6, wn = (wid & 3) << 5;

    float acc[4][4][4];
#pragma unroll
    for (int i = 0; i < 4; i++)
#pragma unroll
        for (int j = 0; j < 4; j++)
#pragma unroll
            for (int e = 0; e < 4; e++) acc[i][j][e] = 0.f;

    int fr[4], fc[4];
#pragma unroll
    for (int i = 0; i < 4; i++) {
        int f = (i << 8) + tid;
        fr[i] = f >> 3;
        fc[i] = (f & 7) << 2;
    }

    // prologue: fill buffer 0
#pragma unroll
    for (int i = 0; i < 4; i++) {
        float4 av = *(const float4*)(A + (size_t)(m0 + fr[i]) * DD + fc[i]);
        st_tf4(sm + fr[i] * 36 + fc[i], av);
        float4 bv = *(const float4*)(W + (size_t)(n0 + fr[i]) * DD + fc[i]);
        st_tf4(sm + 4608 + fr[i] * 36 + fc[i], bv);
    }
    __syncthreads();

    for (int kk = 0; kk < 32; kk++) {
        float* As_ = sm + (kk & 1) * 9216;
        float* Bs_ = As_ + 4608;

        float4 pa[4], pb[4];
        if (kk < 31) {
            int k0n = (kk + 1) << 5;
#pragma unroll
            for (int i = 0; i < 4; i++) {
                pa[i] = *(const float4*)(A + (size_t)(m0 + fr[i]) * DD + k0n + fc[i]);
                pb[i] = *(const float4*)(W + (size_t)(n0 + fr[i]) * DD + k0n + fc[i]);
            }
        }

#pragma unroll
        for (int s = 0; s < 4; s++) {
            const int k0 = s << 3;
            uint32_t af[4][4];
#pragma unroll
            for (int i = 0; i < 4; i++) {
                const float* q = As_ + (wm + (i << 4) + g) * 36 + k0 + c;
                af[i][0] = fau(q[0]);
                af[i][2] = fau(q[4]);
                af[i][1] = fau(q[8 * 36]);
                af[i][3] = fau(q[8 * 36 + 4]);
            }
#pragma unroll
            for (int j = 0; j < 4; j++) {
                const float* r = Bs_ + (wn + (j << 3) + g) * 36 + k0 + c;
                uint32_t bf[2] = {fau(r[0]), fau(r[4])};
#pragma unroll
                for (int i = 0; i < 4; i++) mma8(acc[i][j], af[i], bf);
            }
        }

        if (kk < 31) {
            __syncthreads();
            float* Ad = sm + ((kk + 1) & 1) * 9216;
            float* Bd = Ad + 4608;
#pragma unroll
            for (int i = 0; i < 4; i++) {
                st_tf4(Ad + fr[i] * 36 + fc[i], pa[i]);
                st_tf4(Bd + fr[i] * 36 + fc[i], pb[i]);
            }
            __syncthreads();
        }
    }

    // epilogue: direct float2 stores from fragments
#pragma unroll
    for (int i = 0; i < 4; i++) {
        int r0 = m0 + wm + (i << 4) + g;
        int r1 = r0 + 8;
#pragma unroll
        for (int j = 0; j < 4; j++) {
            int cb = n0 + wn + (j << 3) + (c << 1);
            if (reshape) {
                int h = cb >> 6, d = cb & 63;
                int b0r = r0 >> 11, s0r = r0 & 2047;
                int b1r = r1 >> 11, s1r = r1 & 2047;
                *(float2*)(out + ((size_t)((b0r * HH + h) * SS + s0r)) * HDIM + d) =
                    make_float2(acc[i][j][0], acc[i][j][1]);
                *(float2*)(out + ((size_t)((b1r * HH + h) * SS + s1r)) * HDIM + d) =
                    make_float2(acc[i][j][2], acc[i][j][3]);
            } else {
                float bb0 = bias ? bias[cb] : 0.f;
                float bb1 = bias ? bias[cb + 1] : 0.f;
                *(float2*)(out + (size_t)r0 * DD + cb) =
                    make_float2(acc[i][j][0] + bb0, acc[i][j][1] + bb1);
                *(float2*)(out + (size_t)r1 * DD + cb) =
                    make_float2(acc[i][j][2] + bb0, acc[i][j][3] + bb1);
            }
        }
    }
}

// ---------------------------------------------------------------------------
// Causal flash attention on tf32 mma. 128 threads (4 warps), q-tile 64,
// k-tile 64. Warp w owns rows [16w,16w+16): softmax stats are quad-local.
// smem: Q/K/P stride 68 (conflict-free A/B frags), V stride 72 (conflict-free
// PV B-frags). P written tf32 by the same warp that consumes it (__syncwarp).
// ---------------------------------------------------------------------------
#define ATTN_SMEM (70656)   // floats: Q 4352 + K 4352 + P 4352 + V 4608

__global__ void __launch_bounds__(128)
attn_kernel(float* __restrict__ ctx)
{
    extern __shared__ float sm[];
    float* smQ = sm;
    float* smK = sm + 4352;
    float* smP = sm + 8704;
    float* smV = sm + 13056;

    const int tid = threadIdx.x;
    const int wid = tid >> 5, lane = tid & 31;
    const int g = lane >> 2, c = lane & 3;
    const int mb = wid << 4;
    const int bh = blockIdx.y;
    const int q0 = blockIdx.x << 6;

    const float* Qb = g_q + (size_t)bh * SS * HDIM;
    const float* Kb = g_k + (size_t)bh * SS * HDIM;
    const float* Vb = g_v + (size_t)bh * SS * HDIM;

    // Q fill (tf32)
#pragma unroll
    for (int i = 0; i < 8; i++) {
        int f = (i << 7) + tid;
        int r = f >> 4, c4 = (f & 15) << 2;
        float4 v = *(const float4*)(Qb + (size_t)(q0 + r) * HDIM + c4);
        st_tf4(smQ + r * 68 + c4, v);
    }

    float o[8][4];
#pragma unroll
    for (int j = 0; j < 8; j++)
#pragma unroll
        for (int e = 0; e < 4; e++) o[j][e] = 0.f;
    float m0i = -1e30f, m1i = -1e30f, l0 = 0.f, l1 = 0.f;

    const int row0 = q0 + mb + g;
    const int row1 = row0 + 8;
    const int ktiles = (q0 >> 6) + 1;

    for (int kt = 0; kt < ktiles; kt++) {
        const int kvb = kt << 6;
        __syncthreads();
        // K, V fill (tf32)
#pragma unroll
        for (int i = 0; i < 8; i++) {
            int f = (i << 7) + tid;
            int r = f >> 4, c4 = (f & 15) << 2;
            float4 kv = *(const float4*)(Kb + (size_t)(kvb + r) * HDIM + c4);
            st_tf4(smK + r * 68 + c4, kv);
            float4 vv = *(const float4*)(Vb + (size_t)(kvb + r) * HDIM + c4);
            st_tf4(smV + r * 72 + c4, vv);
        }
        __syncthreads();

        // S = Q K^T
        float s[8][4];
#pragma unroll
        for (int j = 0; j < 8; j++)
#pragma unroll
            for (int e = 0; e < 4; e++) s[j][e] = 0.f;
#pragma unroll
        for (int k0 = 0; k0 < 64; k0 += 8) {
            uint32_t a[4];
            const float* q = smQ + (mb + g) * 68 + k0 + c;
            a[0] = fau(q[0]);
            a[2] = fau(q[4]);
            a[1] = fau(q[8 * 68]);
            a[3] = fau(q[8 * 68 + 4]);
#pragma unroll
            for (int j = 0; j < 8; j++) {
                const float* r = smK + ((j << 3) + g) * 68 + k0 + c;
                uint32_t b[2] = {fau(r[0]), fau(r[4])};
                mma8(s[j], a, b);
            }
        }

        // scale + causal mask
        const bool diag = (kt == ktiles - 1);
#pragma unroll
        for (int j = 0; j < 8; j++) {
            int cg = kvb + (j << 3) + (c << 1);
            s[j][0] *= 0.125f; s[j][1] *= 0.125f;
            s[j][2] *= 0.125f; s[j][3] *= 0.125f;
            if (diag) {
                if (cg > row0)     s[j][0] = -1e30f;
                if (cg + 1 > row0) s[j][1] = -1e30f;
                if (cg > row1)     s[j][2] = -1e30f;
                if (cg + 1 > row1) s[j][3] = -1e30f;
            }
        }

        // row max (quad-local)
        float mx0 = -1e30f, mx1 = -1e30f;
#pragma unroll
        for (int j = 0; j < 8; j++) {
            mx0 = fmaxf(mx0, fmaxf(s[j][0], s[j][1]));
            mx1 = fmaxf(mx1, fmaxf(s[j][2], s[j][3]));
        }
        mx0 = fmaxf(mx0, __shfl_xor_sync(0xffffffffu, mx0, 1));
        mx0 = fmaxf(mx0, __shfl_xor_sync(0xffffffffu, mx0, 2));
        mx1 = fmaxf(mx1, __shfl_xor_sync(0xffffffffu, mx1, 1));
        mx1 = fmaxf(mx1, __shfl_xor_sync(0xffffffffu, mx1, 2));

        float mn0 = fmaxf(m0i, mx0), mn1 = fmaxf(m1i, mx1);
        float al0 = __expf(m0i - mn0), al1 = __expf(m1i - mn1);
        m0i = mn0; m1i = mn1;

        float sum0 = 0.f, sum1 = 0.f;
#pragma unroll
        for (int j = 0; j < 8; j++) {
            s[j][0] = __expf(s[j][0] - mn0);
            s[j][1] = __expf(s[j][1] - mn0);
            s[j][2] = __expf(s[j][2] - mn1);
            s[j][3] = __expf(s[j][3] - mn1);
            sum0 += s[j][0] + s[j][1];
            sum1 += s[j][2] + s[j][3];
        }
        sum0 += __shfl_xor_sync(0xffffffffu, sum0, 1);
        sum0 += __shfl_xor_sync(0xffffffffu, sum0, 2);
        sum1 += __shfl_xor_sync(0xffffffffu, sum1, 1);
        sum1 += __shfl_xor_sync(0xffffffffu, sum1, 2);
        l0 = l0 * al0 + sum0;
        l1 = l1 * al1 + sum1;

#pragma unroll
        for (int j = 0; j < 8; j++) {
            o[j][0] *= al0; o[j][1] *= al0;
            o[j][2] *= al1; o[j][3] *= al1;
        }

        // P -> smem (tf32), own rows only
        float* p0 = smP + (mb + g) * 68 + (c << 1);
        float* p1 = smP + (mb + g + 8) * 68 + (c << 1);
#pragma unroll
        for (int j = 0; j < 8; j++) {
            *(uint2*)(p0 + (j << 3)) = make_uint2(f2tf(s[j][0]), f2tf(s[j][1]));
            *(uint2*)(p1 + (j << 3)) = make_uint2(f2tf(s[j][2]), f2tf(s[j][3]));
        }
        __syncwarp();

        // O += P V
#pragma unroll
        for (int k0 = 0; k0 < 64; k0 += 8) {
            uint32_t a[4];
            const float* p = smP + (mb + g) * 68 + k0 + c;
            a[0] = fau(p[0]);
            a[2] = fau(p[4]);
            a[1] = fau(p[8 * 68]);
            a[3] = fau(p[8 * 68 + 4]);
#pragma unroll
            for (int j = 0; j < 8; j++) {
                const float* v = smV + (k0 + c) * 72 + (j << 3) + g;
                uint32_t b[2] = {fau(v[0]), fau(v[4 * 72])};
                mma8(o[j], a, b);
            }
        }
    }

    // epilogue
    const int b = bh >> 4, h = bh & 15;
    float inv0 = 1.0f / l0, inv1 = 1.0f / l1;
    float* out0 = ctx + ((size_t)(b * SS + row0)) * DD + (h << 6) + (c << 1);
    float* out1 = ctx + ((size_t)(b * SS + row1)) * DD + (h << 6) + (c << 1);
#pragma unroll
    for (int j = 0; j < 8; j++) {
        *(float2*)(out0 + (j << 3)) = make_float2(o[j][0] * inv0, o[j][1] * inv0);
        *(float2*)(out1 + (j << 3)) = make_float2(o[j][2] * inv1, o[j][3] * inv1);
    }
}

// ---------------------------------------------------------------------------
extern "C" void kernel_launch(void* const* d_in, const int* in_sizes, int n_in,
                              void* d_out, int out_size)
{
    const float* x  = (const float*)d_in[0];
    const float* Wq = (const float*)d_in[1];
    const float* Wk = (const float*)d_in[2];
    const float* Wv = (const float*)d_in[3];
    const float* Wo = (const float*)d_in[4];
    const float* bo = (const float*)d_in[5];
    float* out = (float*)d_out;

    float *q_p, *k_p, *v_p, *c_p;
    cudaGetSymbolAddress((void**)&q_p, g_q);
    cudaGetSymbolAddress((void**)&k_p, g_k);
    cudaGetSymbolAddress((void**)&v_p, g_v);
    cudaGetSymbolAddress((void**)&c_p, g_ctx);

    cudaFuncSetAttribute(gemm_tc, cudaFuncAttributeMaxDynamicSharedMemorySize, GEMM_SMEM);
    cudaFuncSetAttribute(attn_kernel, cudaFuncAttributeMaxDynamicSharedMemorySize, ATTN_SMEM);

    dim3 gg(8, 32);   // N/128 x M/128

    gemm_tc<<<gg, 256, GEMM_SMEM>>>(x, Wq, nullptr, q_p, 1);
    gemm_tc<<<gg, 256, GEMM_SMEM>>>(x, Wk, nullptr, k_p, 1);
    gemm_tc<<<gg, 256, GEMM_SMEM>>>(x, Wv, nullptr, v_p, 1);

    attn_kernel<<<dim3(32, 32), 128, ATTN_SMEM>>>(c_p);

    gemm_tc<<<gg, 256, GEMM_SMEM>>>(c_p, Wo, bo, out, 0);
}